// round 3
// baseline (speedup 1.0000x reference)
#include <cuda_runtime.h>
#include <math.h>

// Problem constants
#define TSTEPS 127   // 2W-1 skewed time steps
#define NB 8         // batch
#define NH 64        // H rows
#define NW 64        // W cols
#define HIDC 128     // hidden dim
#define OC 512       // 4*hid gate channels

// Scratch (device globals; no allocation allowed)
__device__ float g_zval[NB * NH * NW * OC];          // [b][p][col][oc]   67 MB, valid positions only
__device__ float g_hhist[(size_t)TSTEPS * NB * NH * HIDC]; // [t][b][p][c]  33.5 MB
__device__ unsigned g_cnt[TSTEPS * 32];              // [t][rowgroup] arrival counters

__device__ __forceinline__ unsigned ld_acquire_gpu(const unsigned* p) {
    unsigned v;
    asm volatile("ld.acquire.gpu.u32 %0, [%1];" : "=r"(v) : "l"(p) : "memory");
    return v;
}

__device__ __forceinline__ float sigmoidf_(float x) {
    return 1.0f / (1.0f + expf(-x));
}

// ---------------------------------------------------------------------------
// Kernel 1: input-to-state 1x1 conv as GEMM over valid (b,p,col) positions.
//   Z[m][o] = sum_c x[b][c][p][col] * w_is[o][c] + b_is[o],  m = (b,p,col)
// M = 32768, K = 128, N = 512. Also zeroes the sync counters (block 0).
// Grid: 1024 blocks = 256 m-tiles x 4 n-tiles, 256 threads, 128KB dyn smem.
// ---------------------------------------------------------------------------
__global__ void __launch_bounds__(256) k_zval(const float* __restrict__ x,
                                              const float* __restrict__ w_is,
                                              const float* __restrict__ b_is) {
    extern __shared__ float sm1[];
    float* Xs = sm1;          // [128 k][128 m]
    float* Ws = sm1 + 16384;  // [128 k][128 o]
    const int tid = threadIdx.x;

    if (blockIdx.x == 0) {
        for (int i = tid; i < TSTEPS * 32; i += 256) g_cnt[i] = 0u;
    }

    const int mt = blockIdx.x >> 2;
    const int nt = blockIdx.x & 3;
    const int m0 = mt * 128;
    const int n0 = nt * 128;
    const int b  = m0 >> 12;       // 4096 (p,col) positions per batch
    const int rem = m0 & 4095;
    const float* xb = x + (size_t)b * 128 * 4096 + rem;

    // load X tile (k-major): Xs[c][mi]
    for (int i = tid * 4; i < 16384; i += 1024) {
        int c = i >> 7, mi = i & 127;
        float4 v = *reinterpret_cast<const float4*>(xb + (size_t)c * 4096 + mi);
        *reinterpret_cast<float4*>(&Xs[c * 128 + mi]) = v;
    }
    // load W tile transposed: Ws[c][oi]
    for (int i = tid * 4; i < 16384; i += 1024) {
        int oi = i >> 7, c4 = i & 127;
        float4 v = *reinterpret_cast<const float4*>(w_is + (size_t)(n0 + oi) * 128 + c4);
        Ws[(c4 + 0) * 128 + oi] = v.x;
        Ws[(c4 + 1) * 128 + oi] = v.y;
        Ws[(c4 + 2) * 128 + oi] = v.z;
        Ws[(c4 + 3) * 128 + oi] = v.w;
    }
    __syncthreads();

    const int tx = tid & 15, ty = tid >> 4;
    const int mi0 = ty * 8, oi0 = tx * 8;
    float acc[8][8];
#pragma unroll
    for (int r = 0; r < 8; ++r)
#pragma unroll
        for (int c = 0; c < 8; ++c) acc[r][c] = 0.0f;

#pragma unroll 4
    for (int k = 0; k < 128; ++k) {
        float a[8], bv[8];
        *reinterpret_cast<float4*>(a)     = *reinterpret_cast<const float4*>(&Xs[k * 128 + mi0]);
        *reinterpret_cast<float4*>(a + 4) = *reinterpret_cast<const float4*>(&Xs[k * 128 + mi0 + 4]);
        *reinterpret_cast<float4*>(bv)     = *reinterpret_cast<const float4*>(&Ws[k * 128 + oi0]);
        *reinterpret_cast<float4*>(bv + 4) = *reinterpret_cast<const float4*>(&Ws[k * 128 + oi0 + 4]);
#pragma unroll
        for (int r = 0; r < 8; ++r)
#pragma unroll
            for (int c = 0; c < 8; ++c) acc[r][c] = fmaf(a[r], bv[c], acc[r][c]);
    }

    float bias[8];
#pragma unroll
    for (int c = 0; c < 8; ++c) bias[c] = b_is[n0 + oi0 + c];

#pragma unroll
    for (int r = 0; r < 8; ++r) {
        float* op = g_zval + (size_t)(m0 + mi0 + r) * OC + n0 + oi0;
        float4 v0, v1;
        v0.x = acc[r][0] + bias[0]; v0.y = acc[r][1] + bias[1];
        v0.z = acc[r][2] + bias[2]; v0.w = acc[r][3] + bias[3];
        v1.x = acc[r][4] + bias[4]; v1.y = acc[r][5] + bias[5];
        v1.z = acc[r][6] + bias[6]; v1.w = acc[r][7] + bias[7];
        *reinterpret_cast<float4*>(op)     = v0;
        *reinterpret_cast<float4*>(op + 4) = v1;
    }
}

// ---------------------------------------------------------------------------
// Kernel 2: persistent recurrence.
// Grid = 128 blocks (all co-resident): blockIdx.x = rg*4 + cg
//   cg  in [0,4): owns hid channels [32*cg, 32*cg+32) across all 4 gates
//   rg  in [0,32): rg = b*4 + pblk, rows p in [16*pblk, 16*pblk+16) of batch b
// Per step t: z = z_is (or b_is) + b_ss + W_slice @ [h_prev_row; h_cur_row],
// then gates, c/h update, h written to g_hhist[t].
// Sync: per-(t,rg) counters; block waits for cnt[t-1][rg]==4 and cnt[t-1][rg-1]==4.
// ---------------------------------------------------------------------------
__global__ void __launch_bounds__(256) k_recur(const float* __restrict__ w_ss,
                                               const float* __restrict__ b_is,
                                               const float* __restrict__ b_ss) {
    extern __shared__ float sm[];
    float* Wsm   = sm;            // [256 k][128 ol]  (k<128: h[p-1] tap, k>=128: h[p] tap)
    float* hPrev = sm + 32768;    // [128 c][18]  rows p0-1 .. p0+14 per local row index
    float* hCur  = hPrev + 2304;  // [128 c][18]  rows p0   .. p0+15
    float* zsm   = hCur + 2304;   // [16 row][128 ol]

    const int tid  = threadIdx.x;
    const int cg   = blockIdx.x & 3;
    const int rg   = blockIdx.x >> 2;
    const int bb   = rg >> 2;
    const int pblk = rg & 3;
    const int p0   = pblk * 16;

    // --- prologue: weight slice into smem ---
    // Wsm[k][ol]: ol -> global out channel og = (ol>>5)*128 + cg*32 + (ol&31)
    // w_ss flat layout: [o][i][kh], kh in {0:prev-row,1:cur-row}
    for (int idx = tid; idx < 128 * 128; idx += 256) {
        int i  = idx & 127;
        int ol = idx >> 7;
        int og = ((ol >> 5) * 128) + cg * 32 + (ol & 31);
        float2 v = *reinterpret_cast<const float2*>(w_ss + (size_t)og * 256 + i * 2);
        Wsm[i * 128 + ol]         = v.x;  // kh=0 tap -> k = i
        Wsm[(i + 128) * 128 + ol] = v.y;  // kh=1 tap -> k = i+128
    }

    const int to = tid & 31;   // output group: ol = 4*to .. 4*to+3 (one gate)
    const int tr = tid >> 5;   // row group: local rows 2*tr, 2*tr+1
    const int ol0 = 4 * to;
    const int og0 = ((ol0 >> 5) * 128) + cg * 32 + (ol0 & 31);

    float4 breg  = *reinterpret_cast<const float4*>(b_ss + og0);
    float4 bireg = *reinterpret_cast<const float4*>(b_is + og0);

    // gate-phase state mapping: states s = 2*tid, 2*tid+1  -> (row, jloc)
    const int srow = (2 * tid) >> 5;       // 0..15
    const int sj0  = (2 * tid) & 31;       // even
    float cst0 = 0.0f, cst1 = 0.0f;

    __syncthreads();

    for (int t = 0; t < TSTEPS; ++t) {
        // --- prefetch z baseline for this thread's 2 rows x 4 channels ---
        float4 zreg[2];
#pragma unroll
        for (int rr = 0; rr < 2; ++rr) {
            int p   = p0 + 2 * tr + rr;
            int col = t - p;
            if (col >= 0 && col < NW) {
                const float* zp = g_zval + (((size_t)(bb * NH + p) * NW + col) * OC);
                zreg[rr] = *reinterpret_cast<const float4*>(zp + og0);
            } else {
                zreg[rr] = bireg;   // skewed zero input -> z_is = b_is
            }
        }

        float acc[2][4];
#pragma unroll
        for (int rr = 0; rr < 2; ++rr)
#pragma unroll
            for (int i = 0; i < 4; ++i) acc[rr][i] = 0.0f;

        if (t > 0) {
            // --- wait for h[t-1] producers ---
            if (tid == 0) {
                const unsigned* c1 = &g_cnt[(t - 1) * 32 + rg];
                while (ld_acquire_gpu(c1) < 4u) {}
                if (pblk > 0) {
                    const unsigned* c2 = c1 - 1;
                    while (ld_acquire_gpu(c2) < 4u) {}
                }
            }
            __syncthreads();

            // --- load 17 h rows (p0-1 .. p0+15), transposed into smem ---
            const float* hb = g_hhist + ((size_t)(t - 1) * NB + bb) * NH * HIDC;
            for (int idx = tid; idx < 2048; idx += 256) {
                int r = idx >> 7;      // 0..15
                int c = idx & 127;
                float v = hb[(size_t)(p0 + r) * HIDC + c];
                hCur[c * 18 + r] = v;
                int rp = p0 + r - 1;
                float vp = (rp >= 0) ? hb[(size_t)rp * HIDC + c] : 0.0f;
                hPrev[c * 18 + r] = vp;
            }
            __syncthreads();

            // --- GEMM: acc[rr][i] += sum_k Wsm[k][ol0+i] * h(k, row rr) ---
#pragma unroll 4
            for (int k = 0; k < 128; ++k) {
                float2 hv = *reinterpret_cast<const float2*>(&hPrev[k * 18 + 2 * tr]);
                float4 wv = *reinterpret_cast<const float4*>(&Wsm[k * 128 + ol0]);
                acc[0][0] = fmaf(hv.x, wv.x, acc[0][0]);
                acc[0][1] = fmaf(hv.x, wv.y, acc[0][1]);
                acc[0][2] = fmaf(hv.x, wv.z, acc[0][2]);
                acc[0][3] = fmaf(hv.x, wv.w, acc[0][3]);
                acc[1][0] = fmaf(hv.y, wv.x, acc[1][0]);
                acc[1][1] = fmaf(hv.y, wv.y, acc[1][1]);
                acc[1][2] = fmaf(hv.y, wv.z, acc[1][2]);
                acc[1][3] = fmaf(hv.y, wv.w, acc[1][3]);
            }
#pragma unroll 4
            for (int k = 0; k < 128; ++k) {
                float2 hv = *reinterpret_cast<const float2*>(&hCur[k * 18 + 2 * tr]);
                float4 wv = *reinterpret_cast<const float4*>(&Wsm[(k + 128) * 128 + ol0]);
                acc[0][0] = fmaf(hv.x, wv.x, acc[0][0]);
                acc[0][1] = fmaf(hv.x, wv.y, acc[0][1]);
                acc[0][2] = fmaf(hv.x, wv.z, acc[0][2]);
                acc[0][3] = fmaf(hv.x, wv.w, acc[0][3]);
                acc[1][0] = fmaf(hv.y, wv.x, acc[1][0]);
                acc[1][1] = fmaf(hv.y, wv.y, acc[1][1]);
                acc[1][2] = fmaf(hv.y, wv.z, acc[1][2]);
                acc[1][3] = fmaf(hv.y, wv.w, acc[1][3]);
            }
        }

        // --- stage pre-activations ---
        {
            float4 z0, z1;
            z0.x = acc[0][0] + zreg[0].x + breg.x;
            z0.y = acc[0][1] + zreg[0].y + breg.y;
            z0.z = acc[0][2] + zreg[0].z + breg.z;
            z0.w = acc[0][3] + zreg[0].w + breg.w;
            z1.x = acc[1][0] + zreg[1].x + breg.x;
            z1.y = acc[1][1] + zreg[1].y + breg.y;
            z1.z = acc[1][2] + zreg[1].z + breg.z;
            z1.w = acc[1][3] + zreg[1].w + breg.w;
            *reinterpret_cast<float4*>(&zsm[(2 * tr) * 128 + ol0])     = z0;
            *reinterpret_cast<float4*>(&zsm[(2 * tr + 1) * 128 + ol0]) = z1;
        }
        __syncthreads();

        // --- gates + state update for this thread's 2 states ---
        {
            const float* zr = &zsm[srow * 128];
            float h0, h1;
            {
                float zi = zr[sj0],      zf = zr[32 + sj0];
                float zo = zr[64 + sj0], zg = zr[96 + sj0];
                float ig = sigmoidf_(zi), fg = sigmoidf_(zf);
                float ogt = sigmoidf_(zo), gg = tanhf(zg);
                cst0 = fg * cst0 + ig * gg;
                h0 = ogt * tanhf(cst0);
            }
            {
                int j = sj0 + 1;
                float zi = zr[j],      zf = zr[32 + j];
                float zo = zr[64 + j], zg = zr[96 + j];
                float ig = sigmoidf_(zi), fg = sigmoidf_(zf);
                float ogt = sigmoidf_(zo), gg = tanhf(zg);
                cst1 = fg * cst1 + ig * gg;
                h1 = ogt * tanhf(cst1);
            }
            int p = p0 + srow;
            float* hw = g_hhist + (((size_t)t * NB + bb) * NH + p) * HIDC + cg * 32 + sj0;
            float2 hv; hv.x = h0; hv.y = h1;
            *reinterpret_cast<float2*>(hw) = hv;
        }

        __threadfence();
        __syncthreads();
        if (tid == 0) {
            atomicAdd(&g_cnt[t * 32 + rg], 1u);
        }
    }
}

// ---------------------------------------------------------------------------
// Kernel 3: unskew + transpose h history into output layout (B, hid, H, W).
//   out[b][c][p][col] = g_hhist[t = p+col][b][p][c]
// Grid: 512 blocks = (b,p), 256 threads, smem transpose tile.
// ---------------------------------------------------------------------------
__global__ void __launch_bounds__(256) k_unskew(float* __restrict__ out) {
    __shared__ float tile[64 * 129];
    const int bp = blockIdx.x;
    const int b = bp >> 6, p = bp & 63;
    const int tid = threadIdx.x;

    for (int idx = tid; idx < 64 * 128; idx += 256) {
        int col = idx >> 7, c = idx & 127;
        int t = p + col;
        tile[col * 129 + c] = g_hhist[(((size_t)t * NB + b) * NH + p) * HIDC + c];
    }
    __syncthreads();
    for (int idx = tid; idx < 64 * 128; idx += 256) {
        int c = idx >> 6, col = idx & 63;
        out[(((size_t)b * HIDC + c) * NH + p) * NW + col] = tile[col * 129 + c];
    }
}

// ---------------------------------------------------------------------------
extern "C" void kernel_launch(void* const* d_in, const int* in_sizes, int n_in,
                              void* d_out, int out_size) {
    const float* x    = (const float*)d_in[0];  // (8,128,64,64)
    const float* w_is = (const float*)d_in[1];  // (512,128)
    const float* b_is = (const float*)d_in[2];  // (512,)
    const float* w_ss = (const float*)d_in[3];  // (512,128,2,1)
    const float* b_ss = (const float*)d_in[4];  // (512,)
    float* out = (float*)d_out;                 // (8,128,64,64)

    static bool attr_set = false;
    // (idempotent host-side config, not device work; safe to set every call)
    cudaFuncSetAttribute(k_zval, cudaFuncAttributeMaxDynamicSharedMemorySize, 131072);
    cudaFuncSetAttribute(k_recur, cudaFuncAttributeMaxDynamicSharedMemorySize, 157696);
    (void)attr_set;

    k_zval<<<1024, 256, 131072>>>(x, w_is, b_is);
    k_recur<<<128, 256, 157696>>>(w_ss, b_is, b_ss);
    k_unskew<<<512, 256>>>(out);

    (void)in_sizes; (void)n_in; (void)out_size;
}